// round 16
// baseline (speedup 1.0000x reference)
#include <cuda_runtime.h>

#define T_LEN   2048
#define BATCH   16
#define NFREQ   1152
#define NOCT    9
#define NF0     128
#define NBP     8

typedef unsigned long long u64;

// -------- device scratch --------
__device__ float g_mag[BATCH * NFREQ];
__device__ int   g_cnt[NBP];              // zero-init; self-resetting each launch

// -------- packed f32x2 helpers --------
__device__ __forceinline__ u64 pk(float lo, float hi) {
    u64 r; asm("mov.b64 %0,{%1,%2};" : "=l"(r) : "f"(lo), "f"(hi)); return r;
}
__device__ __forceinline__ void upk(u64 v, float& lo, float& hi) {
    asm("mov.b64 {%0,%1},%2;" : "=f"(lo), "=f"(hi) : "l"(v));
}
__device__ __forceinline__ u64 bc2(float v) {
    unsigned u = __float_as_uint(v);
    return (u64)u | ((u64)u << 32);
}
__device__ __forceinline__ u64 fma2(u64 a, u64 b, u64 c) {
    u64 d; asm("fma.rn.f32x2 %0,%1,%2,%3;" : "=l"(d) : "l"(a), "l"(b), "l"(c)); return d;
}
__device__ __forceinline__ u64 mul2(u64 a, u64 b) {
    u64 d; asm("mul.rn.f32x2 %0,%1,%2;" : "=l"(d) : "l"(a), "l"(b)); return d;
}
__device__ __forceinline__ u64 add2(u64 a, u64 b) {
    u64 d; asm("add.rn.f32x2 %0,%1,%2;" : "=l"(d) : "l"(a), "l"(b)); return d;
}
__device__ __forceinline__ u64 sub2(u64 a, u64 b) {
    u64 d; asm("sub.rn.f32x2 %0,%1,%2;" : "=l"(d) : "l"(a), "l"(b)); return d;
}
__device__ __forceinline__ float mufu_sin(float x) {
    float r; asm("sin.approx.f32 %0, %1;" : "=f"(r) : "f"(x)); return r;
}
__device__ __forceinline__ float mufu_cos(float x) {
    float r; asm("cos.approx.f32 %0, %1;" : "=f"(r) : "f"(x)); return r;
}

// One packed eval: lanes = TWO BATCHES at the same time index.
// Two MUFU-seeded Chebyshev ladders (octave 0 and octave 5):
//   s' = s*v, v' = v*v - 2  with v = 2cos
// A2 accumulates yn*v == 2*(y*cos); factor 2 removed once in the epilogue.
#define EVAL_PAIR(tv, yn)                                                   \
    do {                                                                    \
        u64 th  = mul2((tv), W0);                                           \
        u64 th2 = mul2((tv), W5);                                           \
        float a0, b0_, a5, b5;                                              \
        upk(th,  a0, b0_);                                                  \
        upk(th2, a5, b5);                                                   \
        u64 s  = pk(mufu_sin(a0), mufu_sin(b0_));                           \
        u64 v  = pk(mufu_cos(a0), mufu_cos(b0_));                           \
        u64 s2 = pk(mufu_sin(a5), mufu_sin(b5));                            \
        u64 v2 = pk(mufu_cos(a5), mufu_cos(b5));                            \
        v  = add2(v, v);                                                    \
        v2 = add2(v2, v2);                                                  \
        A1[0] = fma2((yn), s,  A1[0]);                                      \
        A2[0] = fma2((yn), v,  A2[0]);                                      \
        A1[5] = fma2((yn), s2, A1[5]);                                      \
        A2[5] = fma2((yn), v2, A2[5]);                                      \
        _Pragma("unroll")                                                   \
        for (int k = 1; k < 5; k++) {                                       \
            s = mul2(s, v);                                                 \
            v = fma2(v, v, NEG2);                                           \
            A1[k] = fma2((yn), s, A1[k]);                                   \
            A2[k] = fma2((yn), v, A2[k]);                                   \
        }                                                                   \
        _Pragma("unroll")                                                   \
        for (int k = 6; k < NOCT; k++) {                                    \
            s2 = mul2(s2, v2);                                              \
            v2 = fma2(v2, v2, NEG2);                                        \
            A1[k] = fma2((yn), s2, A1[k]);                                  \
            A2[k] = fma2((yn), v2, A2[k]);                                  \
        }                                                                   \
    } while (0)

// -------- single fused kernel --------
// block (f0, bp): 64 threads = 2 warps; lanes carry batches (2*bp, 2*bp+1).
// Each thread: 32 time steps as 16 float2 iterations, loads 1 iter ahead.
__global__ __launch_bounds__(64) void spectral_kernel(const float* __restrict__ batch,
                                                      const float* __restrict__ freqs,
                                                      float* __restrict__ out) {
    const int f0  = blockIdx.x;
    const int bp  = blockIdx.y;
    const int b0  = 2 * bp, b1 = 2 * bp + 1;
    const int tid = threadIdx.x;
    const int lane = tid & 31, w = tid >> 5;

    __shared__ u64   sredu[2][18];
    __shared__ float rstat[2][2];
    __shared__ float fmean_s, finv_s;
    __shared__ int   last_s;

    // ---- prelude: warp w computes mean of batch (2*bp + w) ----
    {
        const float4* __restrict__ ysw =
            (const float4*)(batch + (2 * bp + w) * (2 * T_LEN) + T_LEN);
        float msum = 0.0f;
#pragma unroll
        for (int i = 0; i < 16; i++) {
            float4 v = __ldg(&ysw[i * 32 + lane]);
            msum += (v.x + v.y) + (v.z + v.w);
        }
#pragma unroll
        for (int o = 16; o; o >>= 1) msum += __shfl_down_sync(0xffffffffu, msum, o);
        if (lane == 0) rstat[w][0] = msum;
    }
    __syncthreads();
    const u64 M = pk(rstat[0][0] * (1.0f / T_LEN), rstat[1][0] * (1.0f / T_LEN));

    const float w0f = freqs[f0] * 6.283185307179586f;   // omega (radians)
    const float w5f = w0f * 32.0f;                      // octave-5 omega
    const u64 W0   = pk(w0f, w0f);
    const u64 W5   = pk(w5f, w5f);
    const u64 NEG2 = bc2(-2.0f);

    u64 A1[NOCT], A2[NOCT];
#pragma unroll
    for (int k = 0; k < NOCT; k++) { A1[k] = 0; A2[k] = 0; }

    const float2* __restrict__ tA = (const float2*)(batch + b0 * (2 * T_LEN));
    const float2* __restrict__ yA = (const float2*)(batch + b0 * (2 * T_LEN) + T_LEN);
    const float2* __restrict__ tB = (const float2*)(batch + b1 * (2 * T_LEN));
    const float2* __restrict__ yB = (const float2*)(batch + b1 * (2 * T_LEN) + T_LEN);

    // ---- main loop: 16 float2 iterations = 32 packed (b0,b1) evals ----
    float2 ta_n = __ldg(&tA[tid]), tb_n = __ldg(&tB[tid]);
    float2 ya_n = __ldg(&yA[tid]), yb_n = __ldg(&yB[tid]);
#pragma unroll 4
    for (int i = 0; i < 16; i++) {
        float2 ta = ta_n, tb = tb_n, ya = ya_n, yb = yb_n;
        if (i < 15) {
            ta_n = __ldg(&tA[(i + 1) * 64 + tid]);
            tb_n = __ldg(&tB[(i + 1) * 64 + tid]);
            ya_n = __ldg(&yA[(i + 1) * 64 + tid]);
            yb_n = __ldg(&yB[(i + 1) * 64 + tid]);
        }
        u64 tvX = pk(ta.x, tb.x), ynX = sub2(pk(ya.x, yb.x), M);
        u64 tvY = pk(ta.y, tb.y), ynY = sub2(pk(ya.y, yb.y), M);
        EVAL_PAIR(tvX, ynX);
        EVAL_PAIR(tvY, ynY);
    }

    // ---- packed butterfly (lanes stay = batches), combine 2 warps ----
#pragma unroll
    for (int k = 0; k < NOCT; k++) {
#pragma unroll
        for (int o = 16; o; o >>= 1) {
            A1[k] = add2(A1[k], __shfl_down_sync(0xffffffffu, A1[k], o));
            A2[k] = add2(A2[k], __shfl_down_sync(0xffffffffu, A2[k], o));
        }
    }
    if (lane == 0) {
#pragma unroll
        for (int k = 0; k < NOCT; k++) {
            sredu[w][k]        = A1[k];
            sredu[w][NOCT + k] = A2[k];
        }
    }
    __syncthreads();

    // ---- write 2 magnitudes per octave (one per batch lane) ----
    if (tid < NOCT) {
        u64 P1 = add2(sredu[0][tid],        sredu[1][tid]);
        u64 P2 = add2(sredu[0][NOCT + tid], sredu[1][NOCT + tid]);
        float p1a, p1b, p2a, p2b;
        upk(P1, p1a, p1b);
        upk(P2, p2a, p2b);
        p2a *= 0.5f; p2b *= 0.5f;
        __stcg(&g_mag[b0 * NFREQ + tid * NF0 + f0], sqrtf(fmaf(p1a, p1a, p2a * p2a)));
        __stcg(&g_mag[b1 * NFREQ + tid * NF0 + f0], sqrtf(fmaf(p1b, p1b, p2b * p2b)));
    }
    __threadfence();
    __syncthreads();
    if (tid == 0) last_s = (atomicAdd(&g_cnt[bp], 1) == NF0 - 1);
    __syncthreads();
    if (!last_s) return;
    __threadfence();

    // ---- last block per batch-pair: tnorm over 1152 freqs for both batches ----
#pragma unroll
    for (int pass = 0; pass < 2; pass++) {
        const int bb = b0 + pass;
        float mv[18];
        float sm = 0.0f, sq2 = 0.0f;
#pragma unroll
        for (int j = 0; j < 18; j++) {
            float v = __ldcg(&g_mag[bb * NFREQ + j * 64 + tid]);
            mv[j] = v;
            sm += v;
            sq2 = fmaf(v, v, sq2);
        }
#pragma unroll
        for (int o = 16; o; o >>= 1) {
            sm  += __shfl_down_sync(0xffffffffu, sm, o);
            sq2 += __shfl_down_sync(0xffffffffu, sq2, o);
        }
        if (lane == 0) { rstat[w][0] = sm; rstat[w][1] = sq2; }
        __syncthreads();
        if (tid == 0) {
            float S = rstat[0][0] + rstat[1][0];
            float Q = rstat[0][1] + rstat[1][1];
            float mean = S * (1.0f / NFREQ);
            float var  = (Q - (float)NFREQ * mean * mean) * (1.0f / (NFREQ - 1));
            fmean_s = mean;
            finv_s  = 1.0f / (sqrtf(var) + 1e-4f);
        }
        __syncthreads();
        const float mmean = fmean_s, minv = finv_s;
#pragma unroll
        for (int j = 0; j < 18; j++)
            out[bb * NFREQ + j * 64 + tid] = (mv[j] - mmean) * minv;
        __syncthreads();   // rstat/fmean reuse across passes
    }
    if (tid == 0) g_cnt[bp] = 0;   // reset for next graph replay
}

// -------- launch --------
extern "C" void kernel_launch(void* const* d_in, const int* in_sizes, int n_in,
                              void* d_out, int out_size) {
    const float* batch = (const float*)d_in[0];   // (16, 2, 2048) f32
    const float* freqs = (const float*)d_in[1];   // (1152,) f32
    float* out = (float*)d_out;                   // (16, 1, 1152) f32

    spectral_kernel<<<dim3(NF0, NBP), 64>>>(batch, freqs, out);
}

// round 17
// speedup vs baseline: 1.7608x; 1.7608x over previous
#include <cuda_runtime.h>

#define T_LEN   2048
#define BATCH   16
#define NFREQ   1152
#define NOCT    9
#define NF0     128

typedef unsigned long long u64;

// -------- device scratch --------
__device__ float g_mag[BATCH * NFREQ];
__device__ int   g_cnt[BATCH];            // zero-init; self-resetting each launch

// -------- packed f32x2 helpers --------
__device__ __forceinline__ u64 pk(float lo, float hi) {
    u64 r; asm("mov.b64 %0,{%1,%2};" : "=l"(r) : "f"(lo), "f"(hi)); return r;
}
__device__ __forceinline__ void upk(u64 v, float& lo, float& hi) {
    asm("mov.b64 {%0,%1},%2;" : "=f"(lo), "=f"(hi) : "l"(v));
}
__device__ __forceinline__ u64 bc2(float v) {
    unsigned u = __float_as_uint(v);
    return (u64)u | ((u64)u << 32);
}
__device__ __forceinline__ u64 fma2(u64 a, u64 b, u64 c) {
    u64 d; asm("fma.rn.f32x2 %0,%1,%2,%3;" : "=l"(d) : "l"(a), "l"(b), "l"(c)); return d;
}
__device__ __forceinline__ u64 mul2(u64 a, u64 b) {
    u64 d; asm("mul.rn.f32x2 %0,%1,%2;" : "=l"(d) : "l"(a), "l"(b)); return d;
}
__device__ __forceinline__ u64 add2(u64 a, u64 b) {
    u64 d; asm("add.rn.f32x2 %0,%1,%2;" : "=l"(d) : "l"(a), "l"(b)); return d;
}
__device__ __forceinline__ u64 sub2(u64 a, u64 b) {
    u64 d; asm("sub.rn.f32x2 %0,%1,%2;" : "=l"(d) : "l"(a), "l"(b)); return d;
}
__device__ __forceinline__ float mufu_sin(float x) {
    float r; asm("sin.approx.f32 %0, %1;" : "=f"(r) : "f"(x)); return r;
}
__device__ __forceinline__ float mufu_cos(float x) {
    float r; asm("cos.approx.f32 %0, %1;" : "=f"(r) : "f"(x)); return r;
}

// One packed pair of time steps across 9 octaves.
// Thetas are SCALAR FMULs feeding MUFU directly (no tv pack/mul2/unpack MOVs).
// Two MUFU-seeded Chebyshev ladders (octave 0 and octave 5):
//   s' = s*v, v' = v*v - 2  with v = 2cos
// A2 accumulates yn*v == 2*(y*cos); factor 2 removed once in the epilogue.
#define EVAL_PAIR(tx, ty, yn)                                               \
    do {                                                                    \
        float t0x = (tx) * w0f, t0y = (ty) * w0f;                           \
        float t5x = t0x * 32.0f, t5y = t0y * 32.0f;                         \
        u64 s  = pk(mufu_sin(t0x), mufu_sin(t0y));                          \
        u64 v  = pk(mufu_cos(t0x), mufu_cos(t0y));                          \
        u64 s2 = pk(mufu_sin(t5x), mufu_sin(t5y));                          \
        u64 v2 = pk(mufu_cos(t5x), mufu_cos(t5y));                          \
        v  = add2(v, v);                                                    \
        v2 = add2(v2, v2);                                                  \
        A1[0] = fma2((yn), s,  A1[0]);                                      \
        A2[0] = fma2((yn), v,  A2[0]);                                      \
        A1[5] = fma2((yn), s2, A1[5]);                                      \
        A2[5] = fma2((yn), v2, A2[5]);                                      \
        _Pragma("unroll")                                                   \
        for (int k = 1; k < 5; k++) {                                       \
            s = mul2(s, v);                                                 \
            v = fma2(v, v, NEG2);                                           \
            A1[k] = fma2((yn), s, A1[k]);                                   \
            A2[k] = fma2((yn), v, A2[k]);                                   \
        }                                                                   \
        _Pragma("unroll")                                                   \
        for (int k = 6; k < NOCT; k++) {                                    \
            s2 = mul2(s2, v2);                                              \
            v2 = fma2(v2, v2, NEG2);                                        \
            A1[k] = fma2((yn), s2, A1[k]);                                  \
            A2[k] = fma2((yn), v2, A2[k]);                                  \
        }                                                                   \
    } while (0)

// -------- single fused kernel --------
// block (f0, b): 64 threads = 2 warps; 4 independent packed pairs per body.
// __launch_bounds__(64, 8): register budget 128/thread -> ptxas can keep the
// 4 eval chains genuinely live (the 64-reg default serialized them).
__global__ __launch_bounds__(64, 8) void spectral_kernel(const float* __restrict__ batch,
                                                         const float* __restrict__ freqs,
                                                         float* __restrict__ out) {
    const int f0  = blockIdx.x;
    const int b   = blockIdx.y;
    const int tid = threadIdx.x;
    const int lane = tid & 31, w = tid >> 5;

    __shared__ float sred[2][18];
    __shared__ float rstat[2][2];
    __shared__ float fmean_s, finv_s;
    __shared__ int   last_s;

    const float4* __restrict__ ts4 = (const float4*)(batch + b * (2 * T_LEN));
    const float4* __restrict__ ys4 = (const float4*)(batch + b * (2 * T_LEN) + T_LEN);

    // ---- slim prelude: block-redundant mean of y (std scale cancels in the
    //      final tnorm; EPS perturbation ~3e-7 relative) ----
    float msum = 0.0f;
#pragma unroll
    for (int i = 0; i < 8; i++) {
        float4 v = __ldg(&ys4[i * 64 + tid]);
        msum += (v.x + v.y) + (v.z + v.w);
    }
#pragma unroll
    for (int o = 16; o; o >>= 1) msum += __shfl_down_sync(0xffffffffu, msum, o);
    if (lane == 0) rstat[w][0] = msum;
    __syncthreads();
    const float m = (rstat[0][0] + rstat[1][0]) * (1.0f / T_LEN);
    const u64 M = pk(m, m);

    const float w0f = freqs[f0] * 6.283185307179586f;   // omega (radians)
    const u64 NEG2 = bc2(-2.0f);

    u64 A1[NOCT], A2[NOCT];
#pragma unroll
    for (int k = 0; k < NOCT; k++) { A1[k] = 0; A2[k] = 0; }

    // ---- main loop: 4 unrolled bodies x 4 packed pairs, loads 2 iters ahead ----
    float4 ta = __ldg(&ts4[tid]),        ya = __ldg(&ys4[tid]);
    float4 tb = __ldg(&ts4[64 + tid]),   yb = __ldg(&ys4[64 + tid]);
#pragma unroll
    for (int i = 0; i < 4; i++) {
        float4 t0 = ta, y0 = ya, t1 = tb, y1 = yb;
        if (i < 3) {
            ta = __ldg(&ts4[(2 * i + 2) * 64 + tid]);
            ya = __ldg(&ys4[(2 * i + 2) * 64 + tid]);
            tb = __ldg(&ts4[(2 * i + 3) * 64 + tid]);
            yb = __ldg(&ys4[(2 * i + 3) * 64 + tid]);
        }
        u64 ynA = sub2(pk(y0.x, y0.y), M);
        u64 ynB = sub2(pk(y0.z, y0.w), M);
        u64 ynC = sub2(pk(y1.x, y1.y), M);
        u64 ynD = sub2(pk(y1.z, y1.w), M);
        EVAL_PAIR(t0.x, t0.y, ynA);
        EVAL_PAIR(t0.z, t0.w, ynB);
        EVAL_PAIR(t1.x, t1.y, ynC);
        EVAL_PAIR(t1.z, t1.w, ynD);
    }

    // ---- fold packed -> scalar first, then 5-stage scalar butterfly ----
    float p[18];
#pragma unroll
    for (int k = 0; k < NOCT; k++) {
        float lo, hi;
        upk(A1[k], lo, hi); p[k]        = lo + hi;
        upk(A2[k], lo, hi); p[NOCT + k] = lo + hi;
    }
#pragma unroll
    for (int j = 0; j < 18; j++) {
#pragma unroll
        for (int o = 16; o; o >>= 1)
            p[j] += __shfl_down_sync(0xffffffffu, p[j], o);
    }
    if (lane == 0) {
#pragma unroll
        for (int j = 0; j < 18; j++) sred[w][j] = p[j];
    }
    __syncthreads();

    // ---- combine 2 warps, write magnitude (P2 carries factor 2 -> halve) ----
    if (tid < NOCT) {
        float P1 = sred[0][tid]        + sred[1][tid];
        float P2 = (sred[0][NOCT + tid] + sred[1][NOCT + tid]) * 0.5f;
        float mg = sqrtf(fmaf(P1, P1, P2 * P2));
        __stcg(&g_mag[b * NFREQ + tid * NF0 + f0], mg);
    }
    __threadfence();
    __syncthreads();
    if (tid == 0) last_s = (atomicAdd(&g_cnt[b], 1) == NF0 - 1);
    __syncthreads();
    if (!last_s) return;
    __threadfence();

    // ---- last block per batch: tnorm over 1152 freqs ----
    float mv[18];
    float sm = 0.0f, sq2 = 0.0f;
#pragma unroll
    for (int j = 0; j < 18; j++) {
        float v = __ldcg(&g_mag[b * NFREQ + j * 64 + tid]);
        mv[j] = v;
        sm += v;
        sq2 = fmaf(v, v, sq2);
    }
#pragma unroll
    for (int o = 16; o; o >>= 1) {
        sm  += __shfl_down_sync(0xffffffffu, sm, o);
        sq2 += __shfl_down_sync(0xffffffffu, sq2, o);
    }
    if (lane == 0) { rstat[w][0] = sm; rstat[w][1] = sq2; }
    __syncthreads();
    if (tid == 0) {
        float S = rstat[0][0] + rstat[1][0];
        float Q = rstat[0][1] + rstat[1][1];
        float mean = S * (1.0f / NFREQ);
        float var  = (Q - (float)NFREQ * mean * mean) * (1.0f / (NFREQ - 1));
        fmean_s = mean;
        finv_s  = 1.0f / (sqrtf(var) + 1e-4f);
        g_cnt[b] = 0;   // reset for next graph replay
    }
    __syncthreads();
    const float mmean = fmean_s, minv = finv_s;
#pragma unroll
    for (int j = 0; j < 18; j++)
        out[b * NFREQ + j * 64 + tid] = (mv[j] - mmean) * minv;
}

// -------- launch --------
extern "C" void kernel_launch(void* const* d_in, const int* in_sizes, int n_in,
                              void* d_out, int out_size) {
    const float* batch = (const float*)d_in[0];   // (16, 2, 2048) f32
    const float* freqs = (const float*)d_in[1];   // (1152,) f32
    float* out = (float*)d_out;                   // (16, 1, 1152) f32

    spectral_kernel<<<dim3(NF0, BATCH), 64>>>(batch, freqs, out);
}